// round 6
// baseline (speedup 1.0000x reference)
#include <cuda_runtime.h>
#include <math.h>

#define BATCH 8
#define SLEN  2048
#define DIM   512
#define MTOT  (BATCH*SLEN)

// ---------------- scratch ----------------
__device__ float g_qlin[MTOT*DIM];
__device__ float g_klin[MTOT*DIM];
__device__ float g_vlin[MTOT*DIM];
__device__ float g_q[MTOT*DIM];
__device__ float g_k[MTOT*DIM];
__device__ float g_v[MTOT*DIM];
__device__ float g_gate[MTOT*DIM];
__device__ float g_gdn[MTOT*DIM];
__device__ float g_fin[MTOT*DIM];
__device__ float g_alpha[MTOT];
__device__ float g_beta[MTOT];

// ---------------- packed f32x2 helpers ----------------
__device__ __forceinline__ unsigned long long fma2_(unsigned long long a,
                                                    unsigned long long b,
                                                    unsigned long long c) {
    unsigned long long d;
    asm("fma.rn.f32x2 %0, %1, %2, %3;" : "=l"(d) : "l"(a), "l"(b), "l"(c));
    return d;
}
__device__ __forceinline__ unsigned long long mul2_(unsigned long long a,
                                                    unsigned long long b) {
    unsigned long long d;
    asm("mul.rn.f32x2 %0, %1, %2;" : "=l"(d) : "l"(a), "l"(b));
    return d;
}
__device__ __forceinline__ unsigned long long pk2_(float lo, float hi) {
    unsigned long long r;
    asm("mov.b64 %0, {%1, %2};" : "=l"(r)
        : "r"(__float_as_uint(lo)), "r"(__float_as_uint(hi)));
    return r;
}
__device__ __forceinline__ void up2_(unsigned long long a, float& lo, float& hi) {
    unsigned int l, h;
    asm("mov.b64 {%0, %1}, %2;" : "=r"(l), "=r"(h) : "l"(a));
    lo = __uint_as_float(l); hi = __uint_as_float(h);
}
__device__ __forceinline__ float hadd2_(unsigned long long a) {
    float lo, hi; up2_(a, lo, hi); return lo + hi;
}
__device__ __forceinline__ float wredsum_(float v) {
    #pragma unroll
    for (int off = 16; off; off >>= 1) v += __shfl_xor_sync(0xffffffffu, v, off);
    return v;
}
__device__ __forceinline__ float silu_(float x) { return x / (1.0f + __expf(-x)); }

// ---------------- GEMM: C[M,512] = A @ W^T + bias, optional SiLU ----------------
// 128x128 tile, BK=16, 256 threads, 8x8 per thread, double-buffered smem.
template<int ACT>
__global__ void __launch_bounds__(256, 2) sgemm_kernel(
    const float* __restrict__ A, const float* __restrict__ W,
    const float* __restrict__ bias, float* __restrict__ C)
{
    __shared__ float As[2][16][140];
    __shared__ float Bs[2][16][140];
    const int tid = threadIdx.x;
    const int m0 = blockIdx.x * 128;
    const int n0 = blockIdx.y * 128;
    const int tx = tid & 15;         // n dir
    const int ty = tid >> 4;         // m dir
    const int lrow = tid >> 1;       // 0..127
    const int lcol = (tid & 1) * 8;  // 0 or 8

    const float* Aptr = A + (size_t)(m0 + lrow) * DIM + lcol;
    const float* Wptr = W + (size_t)(n0 + lrow) * DIM + lcol;

    float4 a0 = *(const float4*)(Aptr + 0);
    float4 a1 = *(const float4*)(Aptr + 4);
    float4 w0 = *(const float4*)(Wptr + 0);
    float4 w1 = *(const float4*)(Wptr + 4);

    unsigned long long acc[8][4];
    #pragma unroll
    for (int i = 0; i < 8; i++)
        #pragma unroll
        for (int j = 0; j < 4; j++) acc[i][j] = 0ULL;

    int buf = 0;
    #pragma unroll 1
    for (int kb = 0; kb < DIM / 16; ++kb) {
        // stage regs -> smem[buf]
        As[buf][lcol+0][lrow] = a0.x; As[buf][lcol+1][lrow] = a0.y;
        As[buf][lcol+2][lrow] = a0.z; As[buf][lcol+3][lrow] = a0.w;
        As[buf][lcol+4][lrow] = a1.x; As[buf][lcol+5][lrow] = a1.y;
        As[buf][lcol+6][lrow] = a1.z; As[buf][lcol+7][lrow] = a1.w;
        Bs[buf][lcol+0][lrow] = w0.x; Bs[buf][lcol+1][lrow] = w0.y;
        Bs[buf][lcol+2][lrow] = w0.z; Bs[buf][lcol+3][lrow] = w0.w;
        Bs[buf][lcol+4][lrow] = w1.x; Bs[buf][lcol+5][lrow] = w1.y;
        Bs[buf][lcol+6][lrow] = w1.z; Bs[buf][lcol+7][lrow] = w1.w;
        __syncthreads();

        if (kb + 1 < DIM / 16) {
            int k0 = (kb + 1) * 16;
            a0 = *(const float4*)(Aptr + k0 + 0);
            a1 = *(const float4*)(Aptr + k0 + 4);
            w0 = *(const float4*)(Wptr + k0 + 0);
            w1 = *(const float4*)(Wptr + k0 + 4);
        }

        const float (*as)[140] = As[buf];
        const float (*bs)[140] = Bs[buf];
        #pragma unroll
        for (int kk = 0; kk < 16; ++kk) {
            float4 af0 = *(const float4*)&as[kk][ty * 8];
            float4 af1 = *(const float4*)&as[kk][ty * 8 + 4];
            float4 bf0 = *(const float4*)&bs[kk][tx * 8];
            float4 bf1 = *(const float4*)&bs[kk][tx * 8 + 4];
            unsigned long long bb[4] = {
                pk2_(bf0.x, bf0.y), pk2_(bf0.z, bf0.w),
                pk2_(bf1.x, bf1.y), pk2_(bf1.z, bf1.w)
            };
            float av[8] = {af0.x, af0.y, af0.z, af0.w, af1.x, af1.y, af1.z, af1.w};
            #pragma unroll
            for (int i = 0; i < 8; i++) {
                unsigned long long am = pk2_(av[i], av[i]);
                #pragma unroll
                for (int j = 0; j < 4; j++)
                    acc[i][j] = fma2_(am, bb[j], acc[i][j]);
            }
        }
        buf ^= 1;
    }

    float4 bs0 = *(const float4*)(bias + n0 + tx * 8);
    float4 bs1 = *(const float4*)(bias + n0 + tx * 8 + 4);
    #pragma unroll
    for (int i = 0; i < 8; i++) {
        float c[8];
        up2_(acc[i][0], c[0], c[1]);
        up2_(acc[i][1], c[2], c[3]);
        up2_(acc[i][2], c[4], c[5]);
        up2_(acc[i][3], c[6], c[7]);
        c[0] += bs0.x; c[1] += bs0.y; c[2] += bs0.z; c[3] += bs0.w;
        c[4] += bs1.x; c[5] += bs1.y; c[6] += bs1.z; c[7] += bs1.w;
        if (ACT == 1) {
            #pragma unroll
            for (int j = 0; j < 8; j++) c[j] = silu_(c[j]);
        }
        float* cp = C + (size_t)(m0 + ty * 8 + i) * DIM + n0 + tx * 8;
        *(float4*)(cp)     = make_float4(c[0], c[1], c[2], c[3]);
        *(float4*)(cp + 4) = make_float4(c[4], c[5], c[6], c[7]);
    }
}

// ---------------- alpha/beta GEMV + sigmoid ----------------
__global__ void __launch_bounds__(256) ab_kernel(
    const float* __restrict__ x,
    const float* __restrict__ Wa, const float* __restrict__ ba,
    const float* __restrict__ Wb, const float* __restrict__ bb,
    float* __restrict__ alpha, float* __restrict__ beta)
{
    const int warp = threadIdx.x >> 5, lane = threadIdx.x & 31;
    const int m = blockIdx.x * 8 + warp;
    const float* xr = x + (size_t)m * DIM;
    float sa = 0.f, sb = 0.f;
    #pragma unroll
    for (int i = 0; i < 4; i++) {
        float4 xv = *(const float4*)(xr + i * 128 + (lane << 2));
        float4 wa = *(const float4*)(Wa + i * 128 + (lane << 2));
        float4 wb = *(const float4*)(Wb + i * 128 + (lane << 2));
        sa += xv.x*wa.x + xv.y*wa.y + xv.z*wa.z + xv.w*wa.w;
        sb += xv.x*wb.x + xv.y*wb.y + xv.z*wb.z + xv.w*wb.w;
    }
    sa = wredsum_(sa);
    sb = wredsum_(sb);
    if (lane == 0) {
        alpha[m] = 1.0f / (1.0f + __expf(-(sa + ba[0])));
        beta[m]  = 1.0f / (1.0f + __expf(-(sb + bb[0])));
    }
}

// ---------------- depthwise causal conv(4) + SiLU (+ optional L2 norm) ----------------
__global__ void __launch_bounds__(128) conv_silu_kernel(
    const float* __restrict__ lin, const float* __restrict__ cw,
    const float* __restrict__ cb, float* __restrict__ outp, int do_l2)
{
    __shared__ float red[4];
    const int m = blockIdx.x;
    const int s = m & (SLEN - 1);
    const int c = threadIdx.x << 2;
    const int lane = threadIdx.x & 31;
    const int warp = threadIdx.x >> 5;

    float w[4][4];
    #pragma unroll
    for (int ch = 0; ch < 4; ++ch) {
        float4 wv = *(const float4*)(cw + (size_t)(c + ch) * 4);
        w[ch][0] = wv.x; w[ch][1] = wv.y; w[ch][2] = wv.z; w[ch][3] = wv.w;
    }
    float4 bv = *(const float4*)(cb + c);
    float y0 = bv.x, y1 = bv.y, y2 = bv.z, y3 = bv.w;
    #pragma unroll
    for (int tau = 0; tau < 4; ++tau) {
        int sp = s - 3 + tau;
        if (sp >= 0) {
            float4 xv = *(const float4*)(lin + (size_t)(m - 3 + tau) * DIM + c);
            y0 += w[0][tau] * xv.x;
            y1 += w[1][tau] * xv.y;
            y2 += w[2][tau] * xv.z;
            y3 += w[3][tau] * xv.w;
        }
    }
    y0 = silu_(y0); y1 = silu_(y1); y2 = silu_(y2); y3 = silu_(y3);
    float sc = 1.0f;
    if (do_l2) {
        float ss = wredsum_(y0*y0 + y1*y1 + y2*y2 + y3*y3);
        if (lane == 0) red[warp] = ss;
        __syncthreads();
        float tot = red[0] + red[1] + red[2] + red[3];
        sc = 1.0f / fmaxf(sqrtf(tot), 1e-12f);
    }
    *(float4*)(outp + (size_t)m * DIM + c) = make_float4(y0*sc, y1*sc, y2*sc, y3*sc);
}

// ---------------- gated delta-rule scan ----------------
// 128 CTAs x 256 threads. Warp = 4 state rows; lane owns cols
// j = m*128 + lane*4 + {0..3}. Z = S / A, rescaled every 16 steps.
// k AND q prefetched 1 step ahead; merged single reduction phase per step:
// 9 dots (zk0-3, zq0-3, kq), packed 16-shfl butterfly + 5-shfl kq.
__global__ void __launch_bounds__(256, 1) scan_kernel(
    const float* __restrict__ qn, const float* __restrict__ kn,
    const float* __restrict__ vn, const float* __restrict__ alpha,
    const float* __restrict__ beta, float* __restrict__ outp)
{
    const int warp = threadIdx.x >> 5;
    const int lane = threadIdx.x & 31;
    const int cta  = blockIdx.x;
    const int b    = cta >> 4;
    const int i0   = ((cta & 15) << 5) + (warp << 2);

    const float* kp = kn + (size_t)b * SLEN * DIM;
    const float* qp = qn + (size_t)b * SLEN * DIM;
    const float* vp = vn + (size_t)b * SLEN * DIM + i0;
    const float* ap = alpha + (size_t)b * SLEN;
    const float* bp = beta  + (size_t)b * SLEN;
    float* op = outp + (size_t)b * SLEN * DIM + i0;

    // output-lane bookkeeping: 4-lane group g = lane>>2; odd groups hold zq.
    const int g = lane >> 2;
    const bool isout = ((lane & 3) == 0) && (g & 1);
    const int h = g >> 1;
    const int orow = ((h & 1) << 1) | (h >> 1);

    unsigned long long z[4][8];
    #pragma unroll
    for (int r = 0; r < 4; r++)
        #pragma unroll
        for (int e = 0; e < 8; e++) z[r][e] = 0ULL;

    unsigned long long kc[8], qc[8];
    {
        const ulonglong2* kq2 = (const ulonglong2*)kp;
        const ulonglong2* qq2 = (const ulonglong2*)qp;
        #pragma unroll
        for (int m = 0; m < 4; m++) {
            ulonglong2 u = kq2[m * 32 + lane];
            kc[2*m] = u.x; kc[2*m+1] = u.y;
            ulonglong2 w = qq2[m * 32 + lane];
            qc[2*m] = w.x; qc[2*m+1] = w.y;
        }
    }

    float A = 1.0f;
    const unsigned FULL = 0xffffffffu;

    #pragma unroll 1
    for (int t = 0; t < SLEN; ++t) {
        // loads: v/a/b (this step), k/q (next step)
        float4 v4 = *(const float4*)(vp + (size_t)t * DIM);
        float at = __ldg(ap + t);
        float bt = __ldg(bp + t);
        unsigned long long kx[8], qx[8];
        {
            int tnx = (t + 1 < SLEN) ? (t + 1) : t;
            const ulonglong2* kq2 = (const ulonglong2*)(kp + (size_t)tnx * DIM);
            const ulonglong2* qq2 = (const ulonglong2*)(qp + (size_t)tnx * DIM);
            #pragma unroll
            for (int m = 0; m < 4; m++) {
                ulonglong2 u = kq2[m * 32 + lane];
                kx[2*m] = u.x; kx[2*m+1] = u.y;
                ulonglong2 w = qq2[m * 32 + lane];
                qx[2*m] = w.x; qx[2*m+1] = w.y;
            }
        }

        // 9 simultaneous dots on Z_old
        unsigned long long zka[4] = {0,0,0,0};
        unsigned long long zqa[4] = {0,0,0,0};
        unsigned long long kqa = 0;
        #pragma unroll
        for (int e = 0; e < 8; e++) {
            zka[0] = fma2_(z[0][e], kc[e], zka[0]);
            zka[1] = fma2_(z[1][e], kc[e], zka[1]);
            zka[2] = fma2_(z[2][e], kc[e], zka[2]);
            zka[3] = fma2_(z[3][e], kc[e], zka[3]);
            zqa[0] = fma2_(z[0][e], qc[e], zqa[0]);
            zqa[1] = fma2_(z[1][e], qc[e], zqa[1]);
            zqa[2] = fma2_(z[2][e], qc[e], zqa[2]);
            zqa[3] = fma2_(z[3][e], qc[e], zqa[3]);
            kqa    = fma2_(kc[e],   qc[e], kqa);
        }
        float a0 = hadd2_(zka[0]), a1 = hadd2_(zka[1]);
        float a2 = hadd2_(zka[2]), a3 = hadd2_(zka[3]);
        float c0 = hadd2_(zqa[0]), c1 = hadd2_(zqa[1]);
        float c2 = hadd2_(zqa[2]), c3 = hadd2_(zqa[3]);
        float kq = hadd2_(kqa);

        // packed 8-value butterfly (16 shfls)
        float p0, p1, p2, p3;
        {
            float x0 = a0 + __shfl_xor_sync(FULL, a0, 16);
            float x1 = a1 + __shfl_xor_sync(FULL, a1, 16);
            float x2 = a2 + __shfl_xor_sync(FULL, a2, 16);
            float x3 = a3 + __shfl_xor_sync(FULL, a3, 16);
            float y0 = c0 + __shfl_xor_sync(FULL, c0, 16);
            float y1 = c1 + __shfl_xor_sync(FULL, c1, 16);
            float y2 = c2 + __shfl_xor_sync(FULL, c2, 16);
            float y3 = c3 + __shfl_xor_sync(FULL, c3, 16);
            bool hi = (lane & 16) != 0;
            p0 = hi ? x1 : x0;
            p1 = hi ? x3 : x2;
            p2 = hi ? y1 : y0;
            p3 = hi ? y3 : y2;
        }
        float r0, r1;
        {
            float x0 = p0 + __shfl_xor_sync(FULL, p0, 8);
            float x1 = p1 + __shfl_xor_sync(FULL, p1, 8);
            float y0 = p2 + __shfl_xor_sync(FULL, p2, 8);
            float y1 = p3 + __shfl_xor_sync(FULL, p3, 8);
            bool hi = (lane & 8) != 0;
            r0 = hi ? x1 : x0;
            r1 = hi ? y1 : y0;
        }
        float s;
        {
            float x0 = r0 + __shfl_xor_sync(FULL, r0, 4);
            float y0 = r1 + __shfl_xor_sync(FULL, r1, 4);
            s = (lane & 4) ? y0 : x0;
        }
        s += __shfl_xor_sync(FULL, s, 2);
        s += __shfl_xor_sync(FULL, s, 1);

        kq = wredsum_(kq);

        float zk0 = __shfl_sync(FULL, s, 0);
        float zk2 = __shfl_sync(FULL, s, 8);
        float zk1 = __shfl_sync(FULL, s, 16);
        float zk3 = __shfl_sync(FULL, s, 24);

        float An  = A * at;
        float rAn = 1.0f / An;
        float ab  = at * bt;
        float w0 = (bt * v4.x - ab * (A * zk0)) * rAn;
        float w1 = (bt * v4.y - ab * (A * zk1)) * rAn;
        float w2 = (bt * v4.z - ab * (A * zk2)) * rAn;
        float w3 = (bt * v4.w - ab * (A * zk3)) * rAn;

        unsigned long long W0 = pk2_(w0, w0), W1 = pk2_(w1, w1);
        unsigned long long W2 = pk2_(w2, w2), W3 = pk2_(w3, w3);
        #pragma unroll
        for (int e = 0; e < 8; e++) {
            z[0][e] = fma2_(W0, kc[e], z[0][e]);
            z[1][e] = fma2_(W1, kc[e], z[1][e]);
            z[2][e] = fma2_(W2, kc[e], z[2][e]);
            z[3][e] = fma2_(W3, kc[e], z[3][e]);
        }

        if (isout) {
            float wr = (h == 0) ? w0 : (h == 1) ? w2 : (h == 2) ? w1 : w3;
            op[(size_t)t * DIM + orow] = An * (s + wr * kq);
        }

        A = An;
        if ((t & 15) == 15) {
            unsigned long long A2 = pk2_(A, A);
            #pragma unroll
            for (int r = 0; r < 4; r++)
                #pragma unroll
                for (int e = 0; e < 8; e++) z[r][e] = mul2_(z[r][e], A2);
            A = 1.0f;
        }

        #pragma unroll
        for (int e = 0; e < 8; e++) { kc[e] = kx[e]; qc[e] = qx[e]; }
    }
}

// ---------------- zero-centered RMSNorm * gate ----------------
__global__ void __launch_bounds__(128) norm_gate_kernel(
    const float* __restrict__ gdn, const float* __restrict__ norm_w,
    const float* __restrict__ gate, float* __restrict__ fin)
{
    __shared__ float rs[4], rq[4];
    const int m = blockIdx.x;
    const int c = threadIdx.x << 2;
    const int lane = threadIdx.x & 31;
    const int warp = threadIdx.x >> 5;

    float4 xv = *(const float4*)(gdn + (size_t)m * DIM + c);
    float s = wredsum_(xv.x + xv.y + xv.z + xv.w);
    float q = wredsum_(xv.x*xv.x + xv.y*xv.y + xv.z*xv.z + xv.w*xv.w);
    if (lane == 0) { rs[warp] = s; rq[warp] = q; }
    __syncthreads();
    float sum = rs[0] + rs[1] + rs[2] + rs[3];
    float sq  = rq[0] + rq[1] + rq[2] + rq[3];
    float mean = sum * (1.0f / DIM);
    float var  = sq * (1.0f / DIM) - mean * mean;
    float inv  = rsqrtf(var + 1e-5f);

    float4 wv = *(const float4*)(norm_w + c);
    float4 gv = *(const float4*)(gate + (size_t)m * DIM + c);
    float4 r;
    r.x = (xv.x - mean) * inv * wv.x * gv.x;
    r.y = (xv.y - mean) * inv * wv.y * gv.y;
    r.z = (xv.z - mean) * inv * wv.z * gv.z;
    r.w = (xv.w - mean) * inv * wv.w * gv.w;
    *(float4*)(fin + (size_t)m * DIM + c) = r;
}

// ---------------- launch ----------------
extern "C" void kernel_launch(void* const* d_in, const int* in_sizes, int n_in,
                              void* d_out, int out_size) {
    const float* x    = (const float*)d_in[0];
    const float* Wq   = (const float*)d_in[1];
    const float* bq   = (const float*)d_in[2];
    const float* Wk   = (const float*)d_in[3];
    const float* bk   = (const float*)d_in[4];
    const float* Wv   = (const float*)d_in[5];
    const float* bv   = (const float*)d_in[6];
    const float* Wa   = (const float*)d_in[7];
    const float* ba   = (const float*)d_in[8];
    const float* Wb   = (const float*)d_in[9];
    const float* bb   = (const float*)d_in[10];
    const float* cwq  = (const float*)d_in[11];
    const float* cbq  = (const float*)d_in[12];
    const float* cwk  = (const float*)d_in[13];
    const float* cbk  = (const float*)d_in[14];
    const float* cwv  = (const float*)d_in[15];
    const float* cbv  = (const float*)d_in[16];
    const float* norm_w = (const float*)d_in[17];
    const float* Wg   = (const float*)d_in[18];
    const float* bg   = (const float*)d_in[19];
    const float* Wo   = (const float*)d_in[20];
    const float* bo   = (const float*)d_in[21];
    float* out = (float*)d_out;

    float *qlin, *klin, *vlin, *qn, *kn, *vn, *gate, *gdn, *fin, *al, *be;
    cudaGetSymbolAddress((void**)&qlin, g_qlin);
    cudaGetSymbolAddress((void**)&klin, g_klin);
    cudaGetSymbolAddress((void**)&vlin, g_vlin);
    cudaGetSymbolAddress((void**)&qn,   g_q);
    cudaGetSymbolAddress((void**)&kn,   g_k);
    cudaGetSymbolAddress((void**)&vn,   g_v);
    cudaGetSymbolAddress((void**)&gate, g_gate);
    cudaGetSymbolAddress((void**)&gdn,  g_gdn);
    cudaGetSymbolAddress((void**)&fin,  g_fin);
    cudaGetSymbolAddress((void**)&al,   g_alpha);
    cudaGetSymbolAddress((void**)&be,   g_beta);

    dim3 gg(MTOT / 128, DIM / 128);
    sgemm_kernel<0><<<gg, 256>>>(x, Wq, bq, qlin);
    sgemm_kernel<0><<<gg, 256>>>(x, Wk, bk, klin);
    sgemm_kernel<0><<<gg, 256>>>(x, Wv, bv, vlin);
    sgemm_kernel<1><<<gg, 256>>>(x, Wg, bg, gate);
    ab_kernel<<<MTOT / 8, 256>>>(x, Wa, ba, Wb, bb, al, be);

    conv_silu_kernel<<<MTOT, 128>>>(qlin, cwq, cbq, qn, 1);
    conv_silu_kernel<<<MTOT, 128>>>(klin, cwk, cbk, kn, 1);
    conv_silu_kernel<<<MTOT, 128>>>(vlin, cwv, cbv, vn, 0);

    scan_kernel<<<128, 256>>>(qn, kn, vn, al, be, gdn);

    norm_gate_kernel<<<MTOT, 128>>>(gdn, norm_w, gate, fin);
    sgemm_kernel<0><<<gg, 256>>>(fin, Wo, bo, out);
}

// round 7
// speedup vs baseline: 1.1424x; 1.1424x over previous
#include <cuda_runtime.h>
#include <math.h>

#define BATCH 8
#define SLEN  2048
#define DIM   512
#define MTOT  (BATCH*SLEN)

// ---------------- scratch ----------------
__device__ float g_qlin[MTOT*DIM];
__device__ float g_klin[MTOT*DIM];
__device__ float g_vlin[MTOT*DIM];
__device__ float g_q[MTOT*DIM];
__device__ float g_k[MTOT*DIM];
__device__ float g_v[MTOT*DIM];
__device__ float g_gate[MTOT*DIM];
__device__ float g_gdn[MTOT*DIM];
__device__ float g_fin[MTOT*DIM];
__device__ float g_alpha[MTOT];
__device__ float g_beta[MTOT];

// ---------------- packed f32x2 helpers ----------------
__device__ __forceinline__ unsigned long long fma2_(unsigned long long a,
                                                    unsigned long long b,
                                                    unsigned long long c) {
    unsigned long long d;
    asm("fma.rn.f32x2 %0, %1, %2, %3;" : "=l"(d) : "l"(a), "l"(b), "l"(c));
    return d;
}
__device__ __forceinline__ unsigned long long mul2_(unsigned long long a,
                                                    unsigned long long b) {
    unsigned long long d;
    asm("mul.rn.f32x2 %0, %1, %2;" : "=l"(d) : "l"(a), "l"(b));
    return d;
}
__device__ __forceinline__ unsigned long long pk2_(float lo, float hi) {
    unsigned long long r;
    asm("mov.b64 %0, {%1, %2};" : "=l"(r)
        : "r"(__float_as_uint(lo)), "r"(__float_as_uint(hi)));
    return r;
}
__device__ __forceinline__ void up2_(unsigned long long a, float& lo, float& hi) {
    unsigned int l, h;
    asm("mov.b64 {%0, %1}, %2;" : "=r"(l), "=r"(h) : "l"(a));
    lo = __uint_as_float(l); hi = __uint_as_float(h);
}
__device__ __forceinline__ float hadd2_(unsigned long long a) {
    float lo, hi; up2_(a, lo, hi); return lo + hi;
}
__device__ __forceinline__ float wredsum_(float v) {
    #pragma unroll
    for (int off = 16; off; off >>= 1) v += __shfl_xor_sync(0xffffffffu, v, off);
    return v;
}
__device__ __forceinline__ float silu_(float x) { return x / (1.0f + __expf(-x)); }
__device__ __forceinline__ void cpasync16_(unsigned int dst, const void* src) {
    asm volatile("cp.async.cg.shared.global [%0], [%1], 16;"
                 :: "r"(dst), "l"(src) : "memory");
}

// ---------------- GEMM: C[M,512] = A @ W^T + bias, optional SiLU ----------------
// 128x128 tile, BK=16, 256 threads, 8x8 per thread, double-buffered smem.
template<int ACT>
__global__ void __launch_bounds__(256, 2) sgemm_kernel(
    const float* __restrict__ A, const float* __restrict__ W,
    const float* __restrict__ bias, float* __restrict__ C)
{
    __shared__ float As[2][16][140];
    __shared__ float Bs[2][16][140];
    const int tid = threadIdx.x;
    const int m0 = blockIdx.x * 128;
    const int n0 = blockIdx.y * 128;
    const int tx = tid & 15;
    const int ty = tid >> 4;
    const int lrow = tid >> 1;
    const int lcol = (tid & 1) * 8;

    const float* Aptr = A + (size_t)(m0 + lrow) * DIM + lcol;
    const float* Wptr = W + (size_t)(n0 + lrow) * DIM + lcol;

    float4 a0 = *(const float4*)(Aptr + 0);
    float4 a1 = *(const float4*)(Aptr + 4);
    float4 w0 = *(const float4*)(Wptr + 0);
    float4 w1 = *(const float4*)(Wptr + 4);

    unsigned long long acc[8][4];
    #pragma unroll
    for (int i = 0; i < 8; i++)
        #pragma unroll
        for (int j = 0; j < 4; j++) acc[i][j] = 0ULL;

    int buf = 0;
    #pragma unroll 1
    for (int kb = 0; kb < DIM / 16; ++kb) {
        As[buf][lcol+0][lrow] = a0.x; As[buf][lcol+1][lrow] = a0.y;
        As[buf][lcol+2][lrow] = a0.z; As[buf][lcol+3][lrow] = a0.w;
        As[buf][lcol+4][lrow] = a1.x; As[buf][lcol+5][lrow] = a1.y;
        As[buf][lcol+6][lrow] = a1.z; As[buf][lcol+7][lrow] = a1.w;
        Bs[buf][lcol+0][lrow] = w0.x; Bs[buf][lcol+1][lrow] = w0.y;
        Bs[buf][lcol+2][lrow] = w0.z; Bs[buf][lcol+3][lrow] = w0.w;
        Bs[buf][lcol+4][lrow] = w1.x; Bs[buf][lcol+5][lrow] = w1.y;
        Bs[buf][lcol+6][lrow] = w1.z; Bs[buf][lcol+7][lrow] = w1.w;
        __syncthreads();

        if (kb + 1 < DIM / 16) {
            int k0 = (kb + 1) * 16;
            a0 = *(const float4*)(Aptr + k0 + 0);
            a1 = *(const float4*)(Aptr + k0 + 4);
            w0 = *(const float4*)(Wptr + k0 + 0);
            w1 = *(const float4*)(Wptr + k0 + 4);
        }

        const float (*as)[140] = As[buf];
        const float (*bs)[140] = Bs[buf];
        #pragma unroll
        for (int kk = 0; kk < 16; ++kk) {
            float4 af0 = *(const float4*)&as[kk][ty * 8];
            float4 af1 = *(const float4*)&as[kk][ty * 8 + 4];
            float4 bf0 = *(const float4*)&bs[kk][tx * 8];
            float4 bf1 = *(const float4*)&bs[kk][tx * 8 + 4];
            unsigned long long bb[4] = {
                pk2_(bf0.x, bf0.y), pk2_(bf0.z, bf0.w),
                pk2_(bf1.x, bf1.y), pk2_(bf1.z, bf1.w)
            };
            float av[8] = {af0.x, af0.y, af0.z, af0.w, af1.x, af1.y, af1.z, af1.w};
            #pragma unroll
            for (int i = 0; i < 8; i++) {
                unsigned long long am = pk2_(av[i], av[i]);
                #pragma unroll
                for (int j = 0; j < 4; j++)
                    acc[i][j] = fma2_(am, bb[j], acc[i][j]);
            }
        }
        buf ^= 1;
    }

    float4 bs0 = *(const float4*)(bias + n0 + tx * 8);
    float4 bs1 = *(const float4*)(bias + n0 + tx * 8 + 4);
    #pragma unroll
    for (int i = 0; i < 8; i++) {
        float c[8];
        up2_(acc[i][0], c[0], c[1]);
        up2_(acc[i][1], c[2], c[3]);
        up2_(acc[i][2], c[4], c[5]);
        up2_(acc[i][3], c[6], c[7]);
        c[0] += bs0.x; c[1] += bs0.y; c[2] += bs0.z; c[3] += bs0.w;
        c[4] += bs1.x; c[5] += bs1.y; c[6] += bs1.z; c[7] += bs1.w;
        if (ACT == 1) {
            #pragma unroll
            for (int j = 0; j < 8; j++) c[j] = silu_(c[j]);
        }
        float* cp = C + (size_t)(m0 + ty * 8 + i) * DIM + n0 + tx * 8;
        *(float4*)(cp)     = make_float4(c[0], c[1], c[2], c[3]);
        *(float4*)(cp + 4) = make_float4(c[4], c[5], c[6], c[7]);
    }
}

// ---------------- alpha/beta GEMV + sigmoid ----------------
__global__ void __launch_bounds__(256) ab_kernel(
    const float* __restrict__ x,
    const float* __restrict__ Wa, const float* __restrict__ ba,
    const float* __restrict__ Wb, const float* __restrict__ bb,
    float* __restrict__ alpha, float* __restrict__ beta)
{
    const int warp = threadIdx.x >> 5, lane = threadIdx.x & 31;
    const int m = blockIdx.x * 8 + warp;
    const float* xr = x + (size_t)m * DIM;
    float sa = 0.f, sb = 0.f;
    #pragma unroll
    for (int i = 0; i < 4; i++) {
        float4 xv = *(const float4*)(xr + i * 128 + (lane << 2));
        float4 wa = *(const float4*)(Wa + i * 128 + (lane << 2));
        float4 wb = *(const float4*)(Wb + i * 128 + (lane << 2));
        sa += xv.x*wa.x + xv.y*wa.y + xv.z*wa.z + xv.w*wa.w;
        sb += xv.x*wb.x + xv.y*wb.y + xv.z*wb.z + xv.w*wb.w;
    }
    sa = wredsum_(sa);
    sb = wredsum_(sb);
    if (lane == 0) {
        alpha[m] = 1.0f / (1.0f + __expf(-(sa + ba[0])));
        beta[m]  = 1.0f / (1.0f + __expf(-(sb + bb[0])));
    }
}

// ---------------- depthwise causal conv(4) + SiLU (+ optional L2 norm) ----------------
__global__ void __launch_bounds__(128) conv_silu_kernel(
    const float* __restrict__ lin, const float* __restrict__ cw,
    const float* __restrict__ cb, float* __restrict__ outp, int do_l2)
{
    __shared__ float red[4];
    const int m = blockIdx.x;
    const int s = m & (SLEN - 1);
    const int c = threadIdx.x << 2;
    const int lane = threadIdx.x & 31;
    const int warp = threadIdx.x >> 5;

    float w[4][4];
    #pragma unroll
    for (int ch = 0; ch < 4; ++ch) {
        float4 wv = *(const float4*)(cw + (size_t)(c + ch) * 4);
        w[ch][0] = wv.x; w[ch][1] = wv.y; w[ch][2] = wv.z; w[ch][3] = wv.w;
    }
    float4 bv = *(const float4*)(cb + c);
    float y0 = bv.x, y1 = bv.y, y2 = bv.z, y3 = bv.w;
    #pragma unroll
    for (int tau = 0; tau < 4; ++tau) {
        int sp = s - 3 + tau;
        if (sp >= 0) {
            float4 xv = *(const float4*)(lin + (size_t)(m - 3 + tau) * DIM + c);
            y0 += w[0][tau] * xv.x;
            y1 += w[1][tau] * xv.y;
            y2 += w[2][tau] * xv.z;
            y3 += w[3][tau] * xv.w;
        }
    }
    y0 = silu_(y0); y1 = silu_(y1); y2 = silu_(y2); y3 = silu_(y3);
    float sc = 1.0f;
    if (do_l2) {
        float ss = wredsum_(y0*y0 + y1*y1 + y2*y2 + y3*y3);
        if (lane == 0) red[warp] = ss;
        __syncthreads();
        float tot = red[0] + red[1] + red[2] + red[3];
        sc = 1.0f / fmaxf(sqrtf(tot), 1e-12f);
    }
    *(float4*)(outp + (size_t)m * DIM + c) = make_float4(y0*sc, y1*sc, y2*sc, y3*sc);
}

// ---------------- gated delta-rule scan ----------------
// 256 CTAs x 256 threads. Warp = 2 state rows; lane owns cols
// j = m*128 + lane*4 + {0..3}. Z = S/A, rescaled every 16 steps.
// k/q staged in shared memory once per CTA per step via double-buffered
// cp.async (each warp previously re-loaded the full 4KB from L1; now the
// CTA loads it once and warps read via LDS). 1 bar + 1 wait per step.
__global__ void __launch_bounds__(256, 2) scan_kernel(
    const float* __restrict__ qn, const float* __restrict__ kn,
    const float* __restrict__ vn, const float* __restrict__ alpha,
    const float* __restrict__ beta, float* __restrict__ outp)
{
    const int warp = threadIdx.x >> 5;
    const int lane = threadIdx.x & 31;
    const int cta  = blockIdx.x;                 // 0..255
    const int b    = cta >> 5;
    const int i0   = ((cta & 31) << 4) + (warp << 1);

    const float* kp = kn + (size_t)b * SLEN * DIM;
    const float* qp = qn + (size_t)b * SLEN * DIM;
    const float* vp = vn + (size_t)b * SLEN * DIM + i0;
    const float* ap = alpha + (size_t)b * SLEN;
    const float* bp = beta  + (size_t)b * SLEN;
    float* op = outp + (size_t)b * SLEN * DIM + i0;

    // smem: 2 buffers x (k:512 floats | q:512 floats)
    __shared__ __align__(16) float sbuf[2][1024];
    unsigned int sbase = (unsigned int)__cvta_generic_to_shared(sbuf);
    const int half = threadIdx.x >> 7;          // 0: copies k, 1: copies q
    const int idx  = threadIdx.x & 127;         // float4 index within half
    const float* gsrc = (half ? qp : kp) + idx * 4;
    const unsigned int d0 = sbase + half * 2048 + idx * 16;

    // prologue: t=0 -> buf0, t=1 -> buf1
    cpasync16_(d0,        gsrc);
    asm volatile("cp.async.commit_group;" ::: "memory");
    cpasync16_(d0 + 4096, gsrc + DIM);
    asm volatile("cp.async.commit_group;" ::: "memory");
    asm volatile("cp.async.wait_group 0;" ::: "memory");
    __syncthreads();

    unsigned long long z[2][8];
    #pragma unroll
    for (int r = 0; r < 2; r++)
        #pragma unroll
        for (int e = 0; e < 8; e++) z[r][e] = 0ULL;

    float A = 1.0f;
    const unsigned FULL = 0xffffffffu;
    const bool h4 = (lane & 16) != 0;

    #pragma unroll 1
    for (int t = 0; t < SLEN; ++t) {
        const int cur = t & 1;

        // read k/q for step t from smem into regs (conflict-free LDS.128)
        unsigned long long kc[8], qc[8];
        {
            const float4* kf = (const float4*)&sbuf[cur][0];
            const float4* qf = (const float4*)&sbuf[cur][512];
            #pragma unroll
            for (int m = 0; m < 4; m++) {
                float4 kv = kf[m * 32 + lane];
                kc[2*m]   = pk2_(kv.x, kv.y);
                kc[2*m+1] = pk2_(kv.z, kv.w);
                float4 qv = qf[m * 32 + lane];
                qc[2*m]   = pk2_(qv.x, qv.y);
                qc[2*m+1] = pk2_(qv.z, qv.w);
            }
        }
        float2 v2 = *(const float2*)(vp + (size_t)t * DIM);
        float at = __ldg(ap + t);
        float bt = __ldg(bp + t);

        // 5 simultaneous dots on Z_old
        unsigned long long zk0a = 0, zk1a = 0, zq0a = 0, zq1a = 0, kqa = 0;
        #pragma unroll
        for (int e = 0; e < 8; e++) {
            zk0a = fma2_(z[0][e], kc[e], zk0a);
            zk1a = fma2_(z[1][e], kc[e], zk1a);
            zq0a = fma2_(z[0][e], qc[e], zq0a);
            zq1a = fma2_(z[1][e], qc[e], zq1a);
            kqa  = fma2_(kc[e],   qc[e], kqa);
        }
        float a0 = hadd2_(zk0a), a1 = hadd2_(zk1a);
        float c0 = hadd2_(zq0a), c1 = hadd2_(zq1a);
        float kq = hadd2_(kqa);

        // packed butterfly
        float x0 = a0 + __shfl_xor_sync(FULL, a0, 16);
        float x1 = a1 + __shfl_xor_sync(FULL, a1, 16);
        float y0 = c0 + __shfl_xor_sync(FULL, c0, 16);
        float y1 = c1 + __shfl_xor_sync(FULL, c1, 16);
        kq += __shfl_xor_sync(FULL, kq, 16);
        float Aa = h4 ? x1 : x0;
        float Bb = h4 ? y1 : y0;
        Aa += __shfl_xor_sync(FULL, Aa, 8);
        Bb += __shfl_xor_sync(FULL, Bb, 8);
        kq += __shfl_xor_sync(FULL, kq, 8);
        float s = (lane & 8) ? Bb : Aa;
        s  += __shfl_xor_sync(FULL, s, 4);
        kq += __shfl_xor_sync(FULL, kq, 4);
        s  += __shfl_xor_sync(FULL, s, 2);
        kq += __shfl_xor_sync(FULL, kq, 2);
        s  += __shfl_xor_sync(FULL, s, 1);
        kq += __shfl_xor_sync(FULL, kq, 1);

        float zk0 = __shfl_sync(FULL, s, 0);
        float zk1 = __shfl_sync(FULL, s, 16);

        float An  = A * at;
        float rAn = 1.0f / An;
        float ab  = at * bt;
        float w0 = (bt * v2.x - ab * (A * zk0)) * rAn;
        float w1 = (bt * v2.y - ab * (A * zk1)) * rAn;

        unsigned long long W0 = pk2_(w0, w0), W1 = pk2_(w1, w1);
        #pragma unroll
        for (int e = 0; e < 8; e++) {
            z[0][e] = fma2_(W0, kc[e], z[0][e]);
            z[1][e] = fma2_(W1, kc[e], z[1][e]);
        }

        // output: lane 8 holds zq0 (row i0), lane 24 holds zq1 (row i0+1)
        if ((lane & 15) == 8) {
            float wr = h4 ? w1 : w0;
            op[(size_t)t * DIM + (h4 ? 1 : 0)] = An * (s + wr * kq);
        }

        A = An;
        if ((t & 15) == 15) {
            unsigned long long A2 = pk2_(A, A);
            #pragma unroll
            for (int r = 0; r < 2; r++)
                #pragma unroll
                for (int e = 0; e < 8; e++) z[r][e] = mul2_(z[r][e], A2);
            A = 1.0f;
        }

        // pipeline: ensure t+1 landed (this thread), then barrier (all warps
        // done reading buf[cur] + t+1 writes visible), then prefetch t+2
        asm volatile("cp.async.wait_group 0;" ::: "memory");
        __syncthreads();
        if (t + 2 < SLEN) {
            cpasync16_(sbase + cur * 4096 + half * 2048 + idx * 16,
                       gsrc + (size_t)(t + 2) * DIM);
        }
        asm volatile("cp.async.commit_group;" ::: "memory");
    }
}

// ---------------- zero-centered RMSNorm * gate ----------------
__global__ void __launch_bounds__(128) norm_gate_kernel(
    const float* __restrict__ gdn, const float* __restrict__ norm_w,
    const float* __restrict__ gate, float* __restrict__ fin)
{
    __shared__ float rs[4], rq[4];
    const int m = blockIdx.x;
    const int c = threadIdx.x << 2;
    const int lane = threadIdx.x & 31;
    const int warp = threadIdx.x >> 5;

    float4 xv = *(const float4*)(gdn + (size_t)m * DIM + c);
    float s = wredsum_(xv.x + xv.y + xv.z + xv.w);
    float q = wredsum_(xv.x*xv.x + xv.y*xv.y + xv.z*xv.z + xv.w*xv.w);
    if (lane == 0) { rs[warp] = s; rq[warp] = q; }
    __syncthreads();
    float sum = rs[0] + rs[1] + rs[2] + rs[3];
    float sq  = rq[0] + rq[1] + rq[2] + rq[3];
    float mean = sum * (1.0f / DIM);
    float var  = sq * (1.0f / DIM) - mean * mean;
    float inv  = rsqrtf(var + 1e-5f);

    float4 wv = *(const float4*)(norm_w + c);
    float4 gv = *(const float4*)(gate + (size_t)m * DIM + c);
    float4 r;
    r.x = (xv.x - mean) * inv * wv.x * gv.x;
    r.y = (xv.y - mean) * inv * wv.y * gv.y;
    r.z = (xv.z - mean) * inv * wv.z * gv.z;
    r.w = (xv.w - mean) * inv * wv.w * gv.w;
    *(float4*)(fin + (size_t)m * DIM + c) = r;
}

// ---------------- launch ----------------
extern "C" void kernel_launch(void* const* d_in, const int* in_sizes, int n_in,
                              void* d_out, int out_size) {
    const float* x    = (const float*)d_in[0];
    const float* Wq   = (const float*)d_in[1];
    const float* bq   = (const float*)d_in[2];
    const float* Wk   = (const float*)d_in[3];
    const float* bk   = (const float*)d_in[4];
    const float* Wv   = (const float*)d_in[5];
    const float* bv   = (const float*)d_in[6];
    const float* Wa   = (const float*)d_in[7];
    const float* ba   = (const float*)d_in[8];
    const float* Wb   = (const float*)d_in[9];
    const float* bb   = (const float*)d_in[10];
    const float* cwq  = (const float*)d_in[11];
    const float* cbq  = (const float*)d_in[12];
    const float* cwk  = (const float*)d_in[13];
    const float* cbk  = (const float*)d_in[14];
    const float* cwv  = (const float*)d_in[15];
    const float* cbv  = (const float*)d_in[16];
    const float* norm_w = (const float*)d_in[17];
    const float* Wg   = (const float*)d_in[18];
    const float* bg   = (const float*)d_in[19];
    const float* Wo   = (const float*)d_in[20];
    const float* bo   = (const float*)d_in[21];
    float* out = (float*)d_out;

    float *qlin, *klin, *vlin, *qn, *kn, *vn, *gate, *gdn, *fin, *al, *be;
    cudaGetSymbolAddress((void**)&qlin, g_qlin);
    cudaGetSymbolAddress((void**)&klin, g_klin);
    cudaGetSymbolAddress((void**)&vlin, g_vlin);
    cudaGetSymbolAddress((void**)&qn,   g_q);
    cudaGetSymbolAddress((void**)&kn,   g_k);
    cudaGetSymbolAddress((void**)&vn,   g_v);
    cudaGetSymbolAddress((void**)&gate, g_gate);
    cudaGetSymbolAddress((void**)&gdn,  g_gdn);
    cudaGetSymbolAddress((void**)&fin,  g_fin);
    cudaGetSymbolAddress((void**)&al,   g_alpha);
    cudaGetSymbolAddress((void**)&be,   g_beta);

    dim3 gg(MTOT / 128, DIM / 128);
    sgemm_kernel<0><<<gg, 256>>>(x, Wq, bq, qlin);
    sgemm_kernel<0><<<gg, 256>>>(x, Wk, bk, klin);
    sgemm_kernel<0><<<gg, 256>>>(x, Wv, bv, vlin);
    sgemm_kernel<1><<<gg, 256>>>(x, Wg, bg, gate);
    ab_kernel<<<MTOT / 8, 256>>>(x, Wa, ba, Wb, bb, al, be);

    conv_silu_kernel<<<MTOT, 128>>>(qlin, cwq, cbq, qn, 1);
    conv_silu_kernel<<<MTOT, 128>>>(klin, cwk, cbk, kn, 1);
    conv_silu_kernel<<<MTOT, 128>>>(vlin, cwv, cbv, vn, 0);

    scan_kernel<<<256, 256>>>(qn, kn, vn, al, be, gdn);

    norm_gate_kernel<<<MTOT, 128>>>(gdn, norm_w, gate, fin);
    sgemm_kernel<0><<<gg, 256>>>(fin, Wo, bo, out);
}